// round 14
// baseline (speedup 1.0000x reference)
#include <cuda_runtime.h>
#include <cuda_bf16.h>
#include <cstdint>

// ---------------------------------------------------------------------------
// Single fused kernel. One block of 256 threads per (batch b, type v, slice):
//   - stage positions of batch b into SoA smem (s_x/s_y/s_z)
//   - scan slice's i-range for rows with z_i == v
//   - prefactor pref[r] = sum_a emb[v,a]*time_rbf(t_b,a)*W[a,r]
//   - sample phi(d) at 2*KNOTS+1 points, fit piecewise quadratic
//     (global form A + B*d + C*d^2) into three 32-word smem arrays
//   - pair phase: WARP-PER-ROW. Each warp owns a row, lanes stride j
//     (conflict-free SoA LDS; table lookup hits one bank row -> no
//     conflicts), single warp-reduce per row, lane 0 writes out+residual.
// All shfls executed by whole warps with uniform control (R10 postmortem).
// ---------------------------------------------------------------------------
#define KNOTS   32
#define DMAXF   16.0f
#define SLICES  4
#define TPB     256
#define NWARPS  (TPB / 32)
#define MAXROWS 256

__device__ __forceinline__ float ex2f_fast(float x) {
    float y; asm("ex2.approx.ftz.f32 %0, %1;" : "=f"(y) : "f"(x)); return y;
}
__device__ __forceinline__ float sqrtf_fast(float x) {
    float y; asm("sqrt.approx.f32 %0, %1;" : "=f"(y) : "f"(x)); return y;
}

template <int RR>
__global__ __launch_bounds__(TPB, 6)
void vf_fused_kernel(const float* __restrict__ pos,
                     const int*   __restrict__ z,
                     const float* __restrict__ t,
                     const float* __restrict__ emb,
                     const float* __restrict__ W,
                     const float* __restrict__ r_off,
                     const float* __restrict__ r_wid,
                     const float* __restrict__ t_off,
                     const float* __restrict__ t_wid,
                     float*       __restrict__ out,
                     int N, int A, int R, int MAXZ) {
    // dynamic smem: SoA positions [N] x 3
    extern __shared__ float smem[];
    float* s_x = smem;
    float* s_y = smem + N;
    float* s_z = smem + 2 * N;

    __shared__ float s_tabA[KNOTS], s_tabB[KNOTS], s_tabC[KNOTS];
    __shared__ float s_phi[2 * KNOTS + 1];
    __shared__ float sx[128];
    __shared__ float s_pref[64], s_k2[64], s_off[64];
    __shared__ int   s_rows[MAXROWS];
    __shared__ int   s_count;

    const float LOG2E = 1.4426950408889634f;
    int bvs   = blockIdx.x;
    int bv    = bvs / SLICES;
    int slice = bvs % SLICES;
    int b     = bv / MAXZ;
    int v     = bv % MAXZ;
    int tid   = threadIdx.x;
    int Ruse  = (RR > 0) ? RR : R;
    int Rpad  = (Ruse + 3) & ~3;

    if (tid == 0) s_count = 0;
    __syncthreads();

    const float* posb = pos + (size_t)b * N * 3;
    bool aligned = ((((unsigned long long)posb) & 15ull) == 0ull);

    // ---- stage positions AoS(gmem) -> SoA(smem): 4 points per thread/iter
    for (int pt = tid * 4; pt < N; pt += TPB * 4) {
        if (aligned && 3 * pt + 12 <= 3 * N) {
            float4 q0 = __ldg((const float4*)(posb + 3 * pt));
            float4 q1 = __ldg((const float4*)(posb + 3 * pt + 4));
            float4 q2 = __ldg((const float4*)(posb + 3 * pt + 8));
            s_x[pt + 0] = q0.x; s_y[pt + 0] = q0.y; s_z[pt + 0] = q0.z;
            s_x[pt + 1] = q0.w; s_y[pt + 1] = q1.x; s_z[pt + 1] = q1.y;
            s_x[pt + 2] = q1.z; s_y[pt + 2] = q1.w; s_z[pt + 2] = q2.x;
            s_x[pt + 3] = q2.y; s_y[pt + 3] = q2.z; s_z[pt + 3] = q2.w;
        } else {
#pragma unroll
            for (int q = 0; q < 4; q++) {
                int p = pt + q;
                if (p < N) {
                    s_x[p] = __ldg(&posb[3 * p + 0]);
                    s_y[p] = __ldg(&posb[3 * p + 1]);
                    s_z[p] = __ldg(&posb[3 * p + 2]);
                }
            }
        }
    }

    // ---- scan slice's i-range ----
    int lo = (int)(((long long)N * slice) / SLICES);
    int hi = (int)(((long long)N * (slice + 1)) / SLICES);
    for (int i = lo + tid; i < hi; i += TPB) {
        if (__ldg(&z[i]) == v) {
            int idx = atomicAdd(&s_count, 1);
            if (idx < MAXROWS) s_rows[idx] = i;
        }
    }

    // ---- small param prep ----
    if (tid < A && tid < 128) {
        float tw = t_wid[tid];
        float dt = t[b] - t_off[tid];
        float c  = (-0.5f / (tw * tw)) * LOG2E;
        sx[tid] = emb[(size_t)v * A + tid] * ex2f_fast(c * dt * dt);
    }
    if (tid < 64) {
        if (tid < Ruse) {
            float w = r_wid[tid];
            s_k2[tid]  = (-0.5f / (w * w)) * LOG2E;
            s_off[tid] = r_off[tid];
        } else {
            s_k2[tid]  = -1.0f;     // padding: pref stays 0 -> inert
            s_off[tid] = 0.0f;
            s_pref[tid] = 0.0f;
        }
    }
    __syncthreads();

    int count = s_count;
    if (count == 0) return;          // uniform across block
    if (count > MAXROWS) count = MAXROWS;

    // ---- prefactor: 4 threads per r (whole warps run the shfls) ----
    {
        int rr  = tid >> 2;
        int sub = tid & 3;
        int rc  = (rr < Ruse) ? rr : (Ruse - 1);
        float s = 0.0f;
        for (int a = sub; a < A; a += 4)
            s = fmaf(sx[a], __ldg(&W[(size_t)a * R + rc]), s);
        s += __shfl_xor_sync(0xFFFFFFFFu, s, 1);
        s += __shfl_xor_sync(0xFFFFFFFFu, s, 2);
        if (sub == 0 && rr < Ruse) s_pref[rr] = s;
    }
    __syncthreads();

    // ---- sample phi at 2*KNOTS+1 points ----
    const float hh = DMAXF / (float)KNOTS;
    if (tid < 2 * KNOTS + 1) {
        float d = (float)tid * (0.5f * hh);
        float a0 = 0.f, a1 = 0.f, a2 = 0.f, a3 = 0.f;
#pragma unroll 1
        for (int r = 0; r < Rpad; r += 4) {
            float e0 = d - s_off[r + 0];
            float e1 = d - s_off[r + 1];
            float e2 = d - s_off[r + 2];
            float e3 = d - s_off[r + 3];
            a0 = fmaf(s_pref[r + 0], ex2f_fast(s_k2[r + 0] * e0 * e0), a0);
            a1 = fmaf(s_pref[r + 1], ex2f_fast(s_k2[r + 1] * e1 * e1), a1);
            a2 = fmaf(s_pref[r + 2], ex2f_fast(s_k2[r + 2] * e2 * e2), a2);
            a3 = fmaf(s_pref[r + 3], ex2f_fast(s_k2[r + 3] * e3 * e3), a3);
        }
        s_phi[tid] = (a0 + a1) + (a2 + a3);
    }
    __syncthreads();

    // ---- fit quadratics (global form A + B*d + C*d^2), SoA table ----
    if (tid < KNOTS) {
        float y0 = s_phi[2 * tid + 0];
        float ym = s_phi[2 * tid + 1];
        float y1 = s_phi[2 * tid + 2];
        float inv_h = 1.0f / hh;
        float d0 = (float)tid * hh;
        float bl = (4.0f * ym - 3.0f * y0 - y1) * inv_h;
        float cl = 2.0f * (y1 - 2.0f * ym + y0) * (inv_h * inv_h);
        s_tabC[tid] = cl;
        s_tabB[tid] = bl - 2.0f * cl * d0;
        s_tabA[tid] = y0 - bl * d0 + cl * d0 * d0;
    }
    __syncthreads();

    // ---- pair phase: WARP-PER-ROW ----
    const float inv_h  = (float)KNOTS / DMAXF;
    const float dclamp = DMAXF - 0.5f * hh;
    int warp = tid >> 5, lane = tid & 31;

    for (int ri = warp; ri < count; ri += NWARPS) {   // uniform per warp
        int i = s_rows[ri];
        float pix = s_x[i];     // broadcast LDS
        float piy = s_y[i];
        float piz = s_z[i];

        float a0 = 0.f, a1 = 0.f, a2 = 0.f;
#pragma unroll 4
        for (int jb = lane; jb < N; jb += 32) {
            float rx = pix - s_x[jb];
            float ry = piy - s_y[jb];
            float rz = piz - s_z[jb];
            float d2 = fmaf(rx, rx, fmaf(ry, ry, fmaf(rz, rz, 1e-6f)));
            float d  = fminf(sqrtf_fast(d2), dclamp);
            int   k  = (int)(d * inv_h);
            float phi = fmaf(fmaf(s_tabC[k], d, s_tabB[k]), d, s_tabA[k]);
            a0 = fmaf(phi, rx, a0);
            a1 = fmaf(phi, ry, a1);
            a2 = fmaf(phi, rz, a2);
        }
#pragma unroll
        for (int off = 16; off > 0; off >>= 1) {
            a0 += __shfl_down_sync(0xFFFFFFFFu, a0, off);
            a1 += __shfl_down_sync(0xFFFFFFFFu, a1, off);
            a2 += __shfl_down_sync(0xFFFFFFFFu, a2, off);
        }
        if (lane == 0) {
            size_t o = ((size_t)b * N + i) * 3;
            out[o + 0] = a0 + pix;
            out[o + 1] = a1 + piy;
            out[o + 2] = a2 + piz;
        }
    }
}

// ---------------------------------------------------------------------------
// Inputs (metadata order):
//  0 positions [B,N,3] f32, 1 t [B] f32, 2 z [N] i32, 3 emb [MAXZ,A] f32,
//  4 W [A,R] f32, 5 rad_off [R], 6 rad_wid [R], 7 time_off [A], 8 time_wid [A]
// ---------------------------------------------------------------------------
extern "C" void kernel_launch(void* const* d_in, const int* in_sizes, int n_in,
                              void* d_out, int out_size) {
    const float* positions = (const float*)d_in[0];
    const float* t         = (const float*)d_in[1];
    const int*   z         = (const int*)  d_in[2];
    const float* emb       = (const float*)d_in[3];
    const float* W         = (const float*)d_in[4];
    const float* r_off     = (const float*)d_in[5];
    const float* r_wid     = (const float*)d_in[6];
    const float* t_off     = (const float*)d_in[7];
    const float* t_wid     = (const float*)d_in[8];

    int B    = in_sizes[1];
    int N    = in_sizes[2];
    int R    = in_sizes[5];
    int A    = in_sizes[7];
    int MAXZ = in_sizes[3] / A;

    int grid = B * MAXZ * SLICES;
    size_t smem = (size_t)3 * N * sizeof(float);

    if (R == 50)
        vf_fused_kernel<50><<<grid, TPB, smem>>>(
            positions, z, t, emb, W, r_off, r_wid, t_off, t_wid,
            (float*)d_out, N, A, R, MAXZ);
    else
        vf_fused_kernel<0><<<grid, TPB, smem>>>(
            positions, z, t, emb, W, r_off, r_wid, t_off, t_wid,
            (float*)d_out, N, A, R, MAXZ);
}

// round 15
// speedup vs baseline: 1.1450x; 1.1450x over previous
#include <cuda_runtime.h>
#include <cuda_bf16.h>
#include <cstdint>

// ---------------------------------------------------------------------------
// Single fused kernel. One block of 512 threads per (batch b, type v, slice):
//   - scan slice's i-range for rows with z_i == v (EARLY EXIT if none)
//   - stage positions of batch b into SoA smem (s_x/s_y/s_z)
//   - prefactor pref[r] = sum_a emb[v,a]*time_rbf(t_b,a)*W[a,r]
//   - sample phi(d) at 2*KNOTS+1 points, fit piecewise quadratic
//     (global form A + B*d + C*d^2) into three 32-word smem arrays
//   - pair phase: WARP-PER-ROW (16 warps cover a slice's rows in one round)
// All shfls executed by whole warps with uniform control (R10 postmortem).
// ---------------------------------------------------------------------------
#define KNOTS   32
#define DMAXF   16.0f
#define SLICES  2
#define TPB     512
#define NWARPS  (TPB / 32)
#define MAXROWS 512

__device__ __forceinline__ float ex2f_fast(float x) {
    float y; asm("ex2.approx.ftz.f32 %0, %1;" : "=f"(y) : "f"(x)); return y;
}
__device__ __forceinline__ float sqrtf_fast(float x) {
    float y; asm("sqrt.approx.f32 %0, %1;" : "=f"(y) : "f"(x)); return y;
}

template <int RR>
__global__ __launch_bounds__(TPB, 3)
void vf_fused_kernel(const float* __restrict__ pos,
                     const int*   __restrict__ z,
                     const float* __restrict__ t,
                     const float* __restrict__ emb,
                     const float* __restrict__ W,
                     const float* __restrict__ r_off,
                     const float* __restrict__ r_wid,
                     const float* __restrict__ t_off,
                     const float* __restrict__ t_wid,
                     float*       __restrict__ out,
                     int N, int A, int R, int MAXZ) {
    // dynamic smem: SoA positions [N] x 3
    extern __shared__ float smem[];
    float* s_x = smem;
    float* s_y = smem + N;
    float* s_z = smem + 2 * N;

    __shared__ float s_tabA[KNOTS], s_tabB[KNOTS], s_tabC[KNOTS];
    __shared__ float s_phi[2 * KNOTS + 1];
    __shared__ float sx[128];
    __shared__ float s_pref[64], s_k2[64], s_off[64];
    __shared__ int   s_rows[MAXROWS];
    __shared__ int   s_count;

    const float LOG2E = 1.4426950408889634f;
    int bvs   = blockIdx.x;
    int bv    = bvs / SLICES;
    int slice = bvs % SLICES;
    int b     = bv / MAXZ;
    int v     = bv % MAXZ;
    int tid   = threadIdx.x;
    int Ruse  = (RR > 0) ? RR : R;
    int Rpad  = (Ruse + 3) & ~3;

    if (tid == 0) s_count = 0;
    __syncthreads();

    // ---- phase 0: scan slice's i-range (cheap), early-exit if empty ----
    int lo = (int)(((long long)N * slice) / SLICES);
    int hi = (int)(((long long)N * (slice + 1)) / SLICES);
    for (int i = lo + tid; i < hi; i += TPB) {
        if (__ldg(&z[i]) == v) {
            int idx = atomicAdd(&s_count, 1);
            if (idx < MAXROWS) s_rows[idx] = i;
        }
    }
    __syncthreads();
    int count = s_count;
    if (count == 0) return;          // uniform across block
    if (count > MAXROWS) count = MAXROWS;

    const float* posb = pos + (size_t)b * N * 3;
    bool aligned = ((((unsigned long long)posb) & 15ull) == 0ull);

    // ---- stage positions AoS(gmem) -> SoA(smem): 4 points per thread/iter
    for (int pt = tid * 4; pt < N; pt += TPB * 4) {
        if (aligned && 3 * pt + 12 <= 3 * N) {
            float4 q0 = __ldg((const float4*)(posb + 3 * pt));
            float4 q1 = __ldg((const float4*)(posb + 3 * pt + 4));
            float4 q2 = __ldg((const float4*)(posb + 3 * pt + 8));
            s_x[pt + 0] = q0.x; s_y[pt + 0] = q0.y; s_z[pt + 0] = q0.z;
            s_x[pt + 1] = q0.w; s_y[pt + 1] = q1.x; s_z[pt + 1] = q1.y;
            s_x[pt + 2] = q1.z; s_y[pt + 2] = q1.w; s_z[pt + 2] = q2.x;
            s_x[pt + 3] = q2.y; s_y[pt + 3] = q2.z; s_z[pt + 3] = q2.w;
        } else {
#pragma unroll
            for (int q = 0; q < 4; q++) {
                int p = pt + q;
                if (p < N) {
                    s_x[p] = __ldg(&posb[3 * p + 0]);
                    s_y[p] = __ldg(&posb[3 * p + 1]);
                    s_z[p] = __ldg(&posb[3 * p + 2]);
                }
            }
        }
    }

    // ---- small param prep (same phase as staging) ----
    if (tid < A && tid < 128) {
        float tw = t_wid[tid];
        float dt = t[b] - t_off[tid];
        float c  = (-0.5f / (tw * tw)) * LOG2E;
        sx[tid] = emb[(size_t)v * A + tid] * ex2f_fast(c * dt * dt);
    }
    if (tid < 64) {
        if (tid < Ruse) {
            float w = r_wid[tid];
            s_k2[tid]  = (-0.5f / (w * w)) * LOG2E;
            s_off[tid] = r_off[tid];
        } else {
            s_k2[tid]  = -1.0f;     // padding: pref stays 0 -> inert
            s_off[tid] = 0.0f;
            s_pref[tid] = 0.0f;
        }
    }
    __syncthreads();

    // ---- prefactor: 4 threads per r (whole warps run the shfls) ----
    if (tid < 256) {
        int rr  = tid >> 2;
        int sub = tid & 3;
        int rc  = (rr < Ruse) ? rr : (Ruse - 1);
        float s = 0.0f;
        for (int a = sub; a < A; a += 4)
            s = fmaf(sx[a], __ldg(&W[(size_t)a * R + rc]), s);
        s += __shfl_xor_sync(0xFFFFFFFFu, s, 1);
        s += __shfl_xor_sync(0xFFFFFFFFu, s, 2);
        if (sub == 0 && rr < Ruse) s_pref[rr] = s;
    }
    __syncthreads();

    // ---- sample phi at 2*KNOTS+1 points ----
    const float hh = DMAXF / (float)KNOTS;
    if (tid < 2 * KNOTS + 1) {
        float d = (float)tid * (0.5f * hh);
        float a0 = 0.f, a1 = 0.f, a2 = 0.f, a3 = 0.f;
#pragma unroll 1
        for (int r = 0; r < Rpad; r += 4) {
            float e0 = d - s_off[r + 0];
            float e1 = d - s_off[r + 1];
            float e2 = d - s_off[r + 2];
            float e3 = d - s_off[r + 3];
            a0 = fmaf(s_pref[r + 0], ex2f_fast(s_k2[r + 0] * e0 * e0), a0);
            a1 = fmaf(s_pref[r + 1], ex2f_fast(s_k2[r + 1] * e1 * e1), a1);
            a2 = fmaf(s_pref[r + 2], ex2f_fast(s_k2[r + 2] * e2 * e2), a2);
            a3 = fmaf(s_pref[r + 3], ex2f_fast(s_k2[r + 3] * e3 * e3), a3);
        }
        s_phi[tid] = (a0 + a1) + (a2 + a3);
    }
    __syncthreads();

    // ---- fit quadratics (global form A + B*d + C*d^2), SoA table ----
    if (tid < KNOTS) {
        float y0 = s_phi[2 * tid + 0];
        float ym = s_phi[2 * tid + 1];
        float y1 = s_phi[2 * tid + 2];
        float inv_h = 1.0f / hh;
        float d0 = (float)tid * hh;
        float bl = (4.0f * ym - 3.0f * y0 - y1) * inv_h;
        float cl = 2.0f * (y1 - 2.0f * ym + y0) * (inv_h * inv_h);
        s_tabC[tid] = cl;
        s_tabB[tid] = bl - 2.0f * cl * d0;
        s_tabA[tid] = y0 - bl * d0 + cl * d0 * d0;
    }
    __syncthreads();

    // ---- pair phase: WARP-PER-ROW (16 warps) ----
    const float inv_h  = (float)KNOTS / DMAXF;
    const float dclamp = DMAXF - 0.5f * hh;
    int warp = tid >> 5, lane = tid & 31;

    for (int ri = warp; ri < count; ri += NWARPS) {   // uniform per warp
        int i = s_rows[ri];
        float pix = s_x[i];     // broadcast LDS
        float piy = s_y[i];
        float piz = s_z[i];

        float a0 = 0.f, a1 = 0.f, a2 = 0.f;
#pragma unroll 4
        for (int jb = lane; jb < N; jb += 32) {
            float rx = pix - s_x[jb];
            float ry = piy - s_y[jb];
            float rz = piz - s_z[jb];
            float d2 = fmaf(rx, rx, fmaf(ry, ry, fmaf(rz, rz, 1e-6f)));
            float d  = fminf(sqrtf_fast(d2), dclamp);
            int   k  = (int)(d * inv_h);
            float phi = fmaf(fmaf(s_tabC[k], d, s_tabB[k]), d, s_tabA[k]);
            a0 = fmaf(phi, rx, a0);
            a1 = fmaf(phi, ry, a1);
            a2 = fmaf(phi, rz, a2);
        }
#pragma unroll
        for (int off = 16; off > 0; off >>= 1) {
            a0 += __shfl_down_sync(0xFFFFFFFFu, a0, off);
            a1 += __shfl_down_sync(0xFFFFFFFFu, a1, off);
            a2 += __shfl_down_sync(0xFFFFFFFFu, a2, off);
        }
        if (lane == 0) {
            size_t o = ((size_t)b * N + i) * 3;
            out[o + 0] = a0 + pix;
            out[o + 1] = a1 + piy;
            out[o + 2] = a2 + piz;
        }
    }
}

// ---------------------------------------------------------------------------
// Inputs (metadata order):
//  0 positions [B,N,3] f32, 1 t [B] f32, 2 z [N] i32, 3 emb [MAXZ,A] f32,
//  4 W [A,R] f32, 5 rad_off [R], 6 rad_wid [R], 7 time_off [A], 8 time_wid [A]
// ---------------------------------------------------------------------------
extern "C" void kernel_launch(void* const* d_in, const int* in_sizes, int n_in,
                              void* d_out, int out_size) {
    const float* positions = (const float*)d_in[0];
    const float* t         = (const float*)d_in[1];
    const int*   z         = (const int*)  d_in[2];
    const float* emb       = (const float*)d_in[3];
    const float* W         = (const float*)d_in[4];
    const float* r_off     = (const float*)d_in[5];
    const float* r_wid     = (const float*)d_in[6];
    const float* t_off     = (const float*)d_in[7];
    const float* t_wid     = (const float*)d_in[8];

    int B    = in_sizes[1];
    int N    = in_sizes[2];
    int R    = in_sizes[5];
    int A    = in_sizes[7];
    int MAXZ = in_sizes[3] / A;

    int grid = B * MAXZ * SLICES;
    size_t smem = (size_t)3 * N * sizeof(float);

    if (R == 50)
        vf_fused_kernel<50><<<grid, TPB, smem>>>(
            positions, z, t, emb, W, r_off, r_wid, t_off, t_wid,
            (float*)d_out, N, A, R, MAXZ);
    else
        vf_fused_kernel<0><<<grid, TPB, smem>>>(
            positions, z, t, emb, W, r_off, r_wid, t_off, t_wid,
            (float*)d_out, N, A, R, MAXZ);
}